// round 16
// baseline (speedup 1.0000x reference)
#include <cuda_runtime.h>
#include <cuda_bf16.h>
#include <cstdint>

#define B_  2
#define T_  2048
#define D_  1024
#define H_  16
#define HD_ 64
#define M_  (B_*T_)   // 4096
#define PITCH 40      // bf16 per smem row: 80B, conflict-free for LDSM

// bf16 hi/lo split operands
__device__ __nv_bfloat16 g_xh[M_*D_],  g_xl[M_*D_];
__device__ __nv_bfloat16 g_qh[M_*D_],  g_ql[M_*D_];
__device__ __nv_bfloat16 g_kh[M_*D_],  g_kl[M_*D_];
__device__ __nv_bfloat16 g_vh[M_*D_],  g_vl[M_*D_];
__device__ __nv_bfloat16 g_ah[M_*D_],  g_al[M_*D_];     // attention out
__device__ __nv_bfloat16 w_qkvh[3*D_*D_], w_qkvl[3*D_*D_];
__device__ __nv_bfloat16 w_oh[D_*D_],  w_ol[D_*D_];

// Fast exp on the FMA pipe.
__device__ __forceinline__ float fexp(float x) {
    float y = fmaxf(x * 1.44269504f, -126.0f);
    float z = y + 12582912.0f;
    int   n = __float_as_int(z) - 0x4B400000;
    float f = y - (z - 12582912.0f);
    float p = 1.3333558e-3f;
    p = fmaf(p, f, 9.6181291e-3f);
    p = fmaf(p, f, 5.5504109e-2f);
    p = fmaf(p, f, 2.4022651e-1f);
    p = fmaf(p, f, 6.9314718e-1f);
    p = fmaf(p, f, 1.0f);
    return p * __int_as_float((n << 23) + 0x3F800000);
}

__device__ __forceinline__ void mma_bf16(float* c, const uint32_t* a, const uint32_t* b) {
    asm volatile(
        "mma.sync.aligned.m16n8k16.row.col.f32.bf16.bf16.f32 "
        "{%0,%1,%2,%3}, {%4,%5,%6,%7}, {%8,%9}, {%0,%1,%2,%3};\n"
        : "+f"(c[0]), "+f"(c[1]), "+f"(c[2]), "+f"(c[3])
        : "r"(a[0]), "r"(a[1]), "r"(a[2]), "r"(a[3]), "r"(b[0]), "r"(b[1]));
}

__device__ __forceinline__ void ldsm_x4(uint32_t& r0, uint32_t& r1, uint32_t& r2,
                                        uint32_t& r3, uint32_t addr) {
    asm volatile("ldmatrix.sync.aligned.m8n8.x4.shared.b16 {%0,%1,%2,%3}, [%4];"
                 : "=r"(r0), "=r"(r1), "=r"(r2), "=r"(r3) : "r"(addr));
}

__device__ __forceinline__ uint32_t smem_u32(const void* p) {
    return (uint32_t)__cvta_generic_to_shared(p);
}

__device__ __forceinline__ void split2(float a, float b, uint32_t& hi, uint32_t& lo) {
    __nv_bfloat16 ah = __float2bfloat16(a);
    __nv_bfloat16 bh = __float2bfloat16(b);
    __nv_bfloat16 al = __float2bfloat16(a - __bfloat162float(ah));
    __nv_bfloat16 bl = __float2bfloat16(b - __bfloat162float(bh));
    hi = (uint32_t)__bfloat16_as_ushort(ah) | ((uint32_t)__bfloat16_as_ushort(bh) << 16);
    lo = (uint32_t)__bfloat16_as_ushort(al) | ((uint32_t)__bfloat16_as_ushort(bl) << 16);
}

__device__ __forceinline__ void cpa16(void* s, const void* g) {
    uint32_t sa = (uint32_t)__cvta_generic_to_shared(s);
    asm volatile("cp.async.ca.shared.global [%0], [%1], 16;\n" :: "r"(sa), "l"(g));
}

// streaming store (evict-first): keeps the 252MB fill out of the GEMM's L2 set
__device__ __forceinline__ void stg_cs4(float* p, float4 v) {
    asm volatile("st.global.cs.v4.f32 [%0], {%1,%2,%3,%4};"
                 :: "l"(p), "f"(v.x), "f"(v.y), "f"(v.z), "f"(v.w) : "memory");
}

// ---------------------------------------------------------------------------
// presplit_all: fp32 -> bf16 hi/lo for x + all four weights, one launch.
// 2 float4 per thread for MLP. Segments: x [0,1048576) then 4 x 262144.
// ---------------------------------------------------------------------------
__global__ void __launch_bounds__(256) presplit_all(
    const float* __restrict__ x,  const float* __restrict__ Wq,
    const float* __restrict__ Wk, const float* __restrict__ Wv,
    const float* __restrict__ Wo)
{
    #pragma unroll
    for (int u = 0; u < 2; u++) {
        int idx = (blockIdx.x * 512) + (u << 8) + threadIdx.x;   // < 2097152
        const float* s;
        __nv_bfloat16 *dh, *dl;
        int off;
        if (idx < 1048576) {
            s = x; dh = g_xh; dl = g_xl; off = idx;
        } else {
            int r = idx - 1048576;
            int w = r >> 18;
            off = r & 262143;
            if (w == 0)      { s = Wq; dh = w_qkvh;             dl = w_qkvl; }
            else if (w == 1) { s = Wk; dh = w_qkvh + D_*D_;     dl = w_qkvl + D_*D_; }
            else if (w == 2) { s = Wv; dh = w_qkvh + 2*D_*D_;   dl = w_qkvl + 2*D_*D_; }
            else             { s = Wo; dh = w_oh;               dl = w_ol; }
        }
        float4 v = ((const float4*)s)[off];
        uint32_t h0, l0, h1, l1;
        split2(v.x, v.y, h0, l0);
        split2(v.z, v.w, h1, l1);
        ((uint2*)dh)[off] = make_uint2(h0, h1);
        ((uint2*)dl)[off] = make_uint2(l0, l1);
    }
}

// ===========================================================================
// 3-stage pipelined GEMM mainloop (shared by gemm_qkv / gemm_out).
// ===========================================================================
#define STG_ (384*PITCH)
#define STGB (STG_*2)       // 30720
#define OAlB (128*PITCH*2)
#define OBhB (256*PITCH*2)
#define OBlB (320*PITCH*2)
#define NSTG 3
#define GSMEM (NSTG*STGB)   // 92160

#define GEMM_PREFETCH(Ahp, Alp, Whp, Wlp)                                         \
    auto prefetch = [&](int kt, int slot) {                                       \
        int k0 = kt << 5;                                                         \
        __nv_bfloat16* st = sm + slot * STG_;                                     \
        _Pragma("unroll")                                                         \
        for (int i = 0; i < 2; i++) {                                             \
            int c = tid + (i << 8);                                               \
            int r = c >> 2, cq = (c & 3) << 3;                                    \
            cpa16(&st[r * PITCH + cq],               &Ahp[(size_t)(bm + r) * D_ + k0 + cq]); \
            cpa16(&st[128 * PITCH + r * PITCH + cq], &Alp[(size_t)(bm + r) * D_ + k0 + cq]); \
        }                                                                         \
        {                                                                         \
            int r = tid >> 2, cq = (tid & 3) << 3;                                \
            cpa16(&st[256 * PITCH + r * PITCH + cq], &Whp[(size_t)(bn + r) * D_ + k0 + cq]); \
            cpa16(&st[320 * PITCH + r * PITCH + cq], &Wlp[(size_t)(bn + r) * D_ + k0 + cq]); \
        }                                                                         \
        asm volatile("cp.async.commit_group;\n");                                 \
    };

#define GEMM_MAINLOOP()                                                           \
    float acc[2][4][4] = {};                                                      \
    prefetch(0, 0);                                                               \
    prefetch(1, 1);                                                               \
    const int KT = D_ / 32;                                                       \
    for (int kt = 0; kt < KT; kt++) {                                             \
        asm volatile("cp.async.wait_group 1;\n");                                 \
        __syncthreads();                                                          \
        if (kt + 2 < KT) prefetch(kt + 2, (kt + 2) % NSTG);                       \
        else asm volatile("cp.async.commit_group;\n");                            \
        const uint32_t stb = smb + (uint32_t)(kt % NSTG) * STGB;                  \
        _Pragma("unroll")                                                         \
        for (int ks = 0; ks < 32; ks += 16) {                                     \
            const uint32_t ka = ks * 2;                                           \
            uint32_t ah[2][4], al[2][4], bh[4][2], bl[4][2];                      \
            ldsm_x4(ah[0][0], ah[0][1], ah[0][2], ah[0][3], stb + aoff0 + ka);    \
            ldsm_x4(ah[1][0], ah[1][1], ah[1][2], ah[1][3], stb + aoff0 + ka + 16 * PITCH * 2); \
            ldsm_x4(al[0][0], al[0][1], al[0][2], al[0][3], stb + OAlB + aoff0 + ka); \
            ldsm_x4(al[1][0], al[1][1], al[1][2], al[1][3], stb + OAlB + aoff0 + ka + 16 * PITCH * 2); \
            ldsm_x4(bh[0][0], bh[0][1], bh[1][0], bh[1][1], stb + OBhB + boff0 + ka); \
            ldsm_x4(bh[2][0], bh[2][1], bh[3][0], bh[3][1], stb + OBhB + boff0 + ka + 16 * PITCH * 2); \
            ldsm_x4(bl[0][0], bl[0][1], bl[1][0], bl[1][1], stb + OBlB + boff0 + ka); \
            ldsm_x4(bl[2][0], bl[2][1], bl[3][0], bl[3][1], stb + OBlB + boff0 + ka + 16 * PITCH * 2); \
            _Pragma("unroll")                                                     \
            for (int mt = 0; mt < 2; mt++)                                        \
                _Pragma("unroll")                                                 \
                for (int nt = 0; nt < 4; nt++) {                                  \
                    mma_bf16(acc[mt][nt], ah[mt], bh[nt]);                        \
                    mma_bf16(acc[mt][nt], ah[mt], bl[nt]);                        \
                    mma_bf16(acc[mt][nt], al[mt], bh[nt]);                        \
                }                                                                 \
        }                                                                         \
    }

// ---------------------------------------------------------------------------
// QKV GEMM with fused bias/RoPE/scale/split epilogue + masked-qk fill.
// The fill is issued FIRST (fire-and-forget streaming stores) so it drains
// underneath the tensor-bound mainloop instead of extending the CTA tail,
// and .cs keeps it from evicting the x/W working set from L2.
// ---------------------------------------------------------------------------
__global__ void __launch_bounds__(256) gemm_qkv(
    const float* __restrict__ cosp, const float* __restrict__ sinp,
    const float* __restrict__ bq, const float* __restrict__ bv,
    float* __restrict__ qkC)
{
    extern __shared__ __align__(16) __nv_bfloat16 sm[];

    const int tid = threadIdx.x, lane = tid & 31, wid = tid >> 5;
    const int wm = (wid & 3) << 5, wn = (wid >> 2) << 5;
    const int bm = blockIdx.y << 7, bn = blockIdx.x << 6;
    const int m8 = lane >> 3, r8 = lane & 7;
    const uint32_t smb = smem_u32(sm);

    const uint32_t aoff0 = ((uint32_t)((wm + r8 + ((m8 & 1) << 3)) * PITCH
                                       + ((m8 >> 1) << 3))) * 2;
    const uint32_t boff0 = ((uint32_t)((wn + r8 + ((m8 >> 1) << 3)) * PITCH
                                       + ((m8 & 1) << 3))) * 2;

    // ---- masked qk fill FIRST: 3840 tiles of 128x128 over 1536 CTAs ----
    {
        const int flat = blockIdx.x + gridDim.x * blockIdx.y;   // 0..1535
        const float4 mv = make_float4(-1e9f, -1e9f, -1e9f, -1e9f);
        for (int t = flat; t < 3840; t += 1536) {
            int bh2 = t / 120;
            int p = t - bh2 * 120;
            int i = 0, a2 = 0;
            while (a2 + (15 - i) <= p) { a2 += (15 - i); i++; }
            int j = p - a2;
            int r0 = i << 7;
            int c0 = ((i + 1 + j) << 7);
            #pragma unroll 4
            for (int e = tid; e < 4096; e += 256) {
                int r = e >> 5, cc = (e & 31) << 2;
                stg_cs4(&qkC[((size_t)bh2 * T_ + r0 + r) * T_ + c0 + cc], mv);
            }
        }
    }

    GEMM_PREFETCH(g_xh, g_xl, w_qkvh, w_qkvl)
    GEMM_MAINLOOP()

    const int seg = bn >> 10;
    __nv_bfloat16* dh = (seg == 0) ? g_qh : (seg == 1) ? g_kh : g_vh;
    __nv_bfloat16* dl = (seg == 0) ? g_ql : (seg == 1) ? g_kl : g_vl;
    const float scale = 0.35355339059327373f;

    #pragma unroll
    for (int mt = 0; mt < 2; mt++) {
        int m0 = bm + wm + (mt << 4) + (lane >> 2);
        int ta = m0 & (T_ - 1), tb = ta + 8;
        #pragma unroll
        for (int nt = 0; nt < 4; nt++) {
            int ng = bn + wn + (nt << 3) + ((lane & 3) << 1);
            int nloc = ng & 1023;
            float v00 = acc[mt][nt][0], v01 = acc[mt][nt][1];
            float v10 = acc[mt][nt][2], v11 = acc[mt][nt][3];
            if (seg == 0) { v00 += bq[nloc]; v01 += bq[nloc + 1];
                            v10 += bq[nloc]; v11 += bq[nloc + 1]; }
            else if (seg == 2) { v00 += bv[nloc]; v01 += bv[nloc + 1];
                                 v10 += bv[nloc]; v11 += bv[nloc + 1]; }
            if (seg < 2) {
                int p = (nloc & 63) >> 1;
                float ca = cosp[ta * 32 + p], sa = sinp[ta * 32 + p];
                float cb = cosp[tb * 32 + p], sb = sinp[tb * 32 + p];
                float o00 = (v00 * ca - v01 * sa) * scale;
                float o01 = (v00 * sa + v01 * ca) * scale;
                float o10 = (v10 * cb - v11 * sb) * scale;
                float o11 = (v10 * sb + v11 * cb) * scale;
                v00 = o00; v01 = o01; v10 = o10; v11 = o11;
            }
            uint32_t h, l;
            split2(v00, v01, h, l);
            *(uint32_t*)&dh[(size_t)m0 * D_ + nloc] = h;
            *(uint32_t*)&dl[(size_t)m0 * D_ + nloc] = l;
            split2(v10, v11, h, l);
            *(uint32_t*)&dh[(size_t)(m0 + 8) * D_ + nloc] = h;
            *(uint32_t*)&dl[(size_t)(m0 + 8) * D_ + nloc] = l;
        }
    }
}

// ---------------------------------------------------------------------------
// Output GEMM: out = wv @ Wo^T + bo (fp32 out)
// ---------------------------------------------------------------------------
__global__ void __launch_bounds__(256) gemm_out(
    const float* __restrict__ bias, float* __restrict__ Cf)
{
    extern __shared__ __align__(16) __nv_bfloat16 sm[];

    const int tid = threadIdx.x, lane = tid & 31, wid = tid >> 5;
    const int wm = (wid & 3) << 5, wn = (wid >> 2) << 5;
    const int bm = blockIdx.y << 7, bn = blockIdx.x << 6;
    const int m8 = lane >> 3, r8 = lane & 7;
    const uint32_t smb = smem_u32(sm);

    const uint32_t aoff0 = ((uint32_t)((wm + r8 + ((m8 & 1) << 3)) * PITCH
                                       + ((m8 >> 1) << 3))) * 2;
    const uint32_t boff0 = ((uint32_t)((wn + r8 + ((m8 >> 1) << 3)) * PITCH
                                       + ((m8 & 1) << 3))) * 2;

    GEMM_PREFETCH(g_ah, g_al, w_oh, w_ol)
    GEMM_MAINLOOP()

    #pragma unroll
    for (int mt = 0; mt < 2; mt++) {
        int m0 = bm + wm + (mt << 4) + (lane >> 2);
        #pragma unroll
        for (int nt = 0; nt < 4; nt++) {
            int n0 = bn + wn + (nt << 3) + ((lane & 3) << 1);
            float b0 = bias[n0], b1 = bias[n0 + 1];
            *(float2*)&Cf[(size_t)m0 * D_ + n0] =
                make_float2(acc[mt][nt][0] + b0, acc[mt][nt][1] + b1);
            *(float2*)&Cf[(size_t)(m0 + 8) * D_ + n0] =
                make_float2(acc[mt][nt][2] + b0, acc[mt][nt][3] + b1);
        }
    }
}

// ---------------------------------------------------------------------------
// Fused attention, FA2-style; longest t-blocks scheduled first.
// ---------------------------------------------------------------------------
#define ATT_SMEM (40960 * 2)

__global__ void __launch_bounds__(256, 2) att_fused(float* __restrict__ qkout)
{
    extern __shared__ __align__(16) __nv_bfloat16 dsm[];

    const int tid  = threadIdx.x;
    const int lane = tid & 31;
    const int w    = tid >> 5;
    const int bh   = blockIdx.y;
    const int b    = bh >> 4, h = bh & 15;
    const int t0   = ((int)(gridDim.x - 1 - blockIdx.x)) << 7;   // longest first
    const int m8 = lane >> 3, r8 = lane & 7;
    const int rA = lane >> 2;
    const int c2 = (lane & 3) << 1;

    const uint32_t smb = smem_u32(dsm);

    const uint32_t aoffQ = ((uint32_t)(((w << 4) + r8 + ((m8 & 1) << 3)) * PITCH
                                       + ((m8 >> 1) << 3))) * 2;
    const uint32_t kboff = ((uint32_t)((r8 + ((m8 >> 1) << 3)) * PITCH
                                       + ((m8 & 1) << 3))) * 2;
    const uint32_t vboff = kboff;

    const __nv_bfloat16* Qh = g_qh + (size_t)b * T_ * D_ + h * HD_;
    const __nv_bfloat16* Ql = g_ql + (size_t)b * T_ * D_ + h * HD_;
    const __nv_bfloat16* Kh = g_kh + (size_t)b * T_ * D_ + h * HD_;
    const __nv_bfloat16* Kl = g_kl + (size_t)b * T_ * D_ + h * HD_;
    const __nv_bfloat16* Vh = g_vh + (size_t)b * T_ * D_ + h * HD_;
    const __nv_bfloat16* Vl = g_vl + (size_t)b * T_ * D_ + h * HD_;

    #pragma unroll
    for (int i = 0; i < 4; i++) {
        int idx = tid + (i << 8);
        int r = idx >> 3, c8 = idx & 7;
        int col = c8 << 3, ch = col >> 5, cc = col & 31;
        int de = ch * 5120 + r * PITCH + cc;
        *(uint4*)&dsm[de]         = *(const uint4*)&Qh[(size_t)(t0 + r) * D_ + col];
        *(uint4*)&dsm[10240 + de] = *(const uint4*)&Ql[(size_t)(t0 + r) * D_ + col];
    }

    auto kfill = [&](int s0, int buf) {
        int r = tid >> 3, c8 = tid & 7;
        int col = c8 << 3, ch = col >> 5, cc = col & 31;
        uint32_t de = 20480 + buf * 5120 + ch * 1280 + r * PITCH + cc;
        cpa16(&dsm[de],        &Kh[(size_t)(s0 + r) * D_ + col]);
        cpa16(&dsm[de + 2560], &Kl[(size_t)(s0 + r) * D_ + col]);
        asm volatile("cp.async.commit_group;\n");
    };

    uint2 vrh[2], vrl[2];
    auto vload = [&](int s0) {
        #pragma unroll
        for (int i = 0; i < 2; i++) {
            int fi = tid + (i << 8);
            int s = fi >> 4, hq = (fi & 15) << 2;
            vrh[i] = *(const uint2*)&Vh[(size_t)(s0 + s) * D_ + hq];
            vrl[i] = *(const uint2*)&Vl[(size_t)(s0 + s) * D_ + hq];
        }
    };
    auto vstore = [&](int buf) {
        #pragma unroll
        for (int i = 0; i < 2; i++) {
            int fi = tid + (i << 8);
            int s = fi >> 4, hq = (fi & 15) << 2;
            const __nv_bfloat16* ph = (const __nv_bfloat16*)&vrh[i];
            const __nv_bfloat16* pl = (const __nv_bfloat16*)&vrl[i];
            #pragma unroll
            for (int j = 0; j < 4; j++) {
                dsm[30720 + buf * 5120 + (hq + j) * PITCH + s]        = ph[j];
                dsm[30720 + buf * 5120 + 2560 + (hq + j) * PITCH + s] = pl[j];
            }
        }
    };

    float aw[8][4] = {};
    float m_a = -1e30f, m_b = -1e30f, rs_a = 0.f, rs_b = 0.f;

    kfill(0, 0);
    vload(0);

    const int ntiles = (t0 >> 5) + 4;
    int cur = 0;
    const int t_a = t0 + (w << 4) + rA;
    const int t_b = t_a + 8;

    for (int it = 0; it < ntiles; it++) {
        const int s0 = it << 5;
        vstore(cur);
        asm volatile("cp.async.wait_group 0;\n");
        __syncthreads();
        if (it + 1 < ntiles) {
            kfill((it + 1) << 5, cur ^ 1);
            vload((it + 1) << 5);
        }

        const bool active = (s0 < t0 + (w << 4) + 16);
        if (active) {
            float aq[4][4] = {};
            #pragma unroll
            for (int c = 0; c < 2; c++) {
                #pragma unroll
                for (int ks = 0; ks < 32; ks += 16) {
                    const uint32_t ka = ks * 2;
                    uint32_t qh4[4], ql4[4], kh2[4][2], kl2[4][2];
                    uint32_t qb = smb + (uint32_t)(c * 10240) + aoffQ + ka;
                    ldsm_x4(qh4[0], qh4[1], qh4[2], qh4[3], qb);
                    ldsm_x4(ql4[0], ql4[1], ql4[2], ql4[3], qb + 20480);
                    uint32_t kb = smb + (uint32_t)((20480 + cur * 5120 + c * 1280) * 2)
                                + kboff + ka;
                    ldsm_x4(kh2[0][0], kh2[0][1], kh2[1][0], kh2[1][1], kb);
                    ldsm_x4(kh2[2][0], kh2[2][1], kh2[3][0], kh2[3][1], kb + 16 * PITCH * 2);
                    ldsm_x4(kl2[0][0], kl2[0][1], kl2[1][0], kl2[1][1], kb + 5120);
                    ldsm_x4(kl2[2][0], kl2[2][1], kl2[3][0], kl2[3][1], kb + 5120 + 16 * PITCH * 2);
                    #pragma unroll
                    for (int nt = 0; nt < 4; nt++) {
                        mma_bf16(aq[nt], qh4, kh2[nt]);
                        mma_bf16(aq[nt], qh4, kl2[nt]);
                        mma_bf16(aq[nt], ql4, kh2[nt]);
                    }
                }
            }

            float rmx_a = -1e30f, rmx_b = -1e30f;
            #pragma unroll
            for (int nt = 0; nt < 4; nt++) {
                int sg = s0 + (nt << 3) + c2;
                float v0 = aq[nt][0] + ((sg     > t_a) ? -1e9f : 0.f);
                float v1 = aq[nt][1] + ((sg + 1 > t_a) ? -1e9f : 0.f);
                float v2 = aq[nt][2] + ((sg     > t_b) ? -1e9f : 0.f);
                float v3 = aq[nt][3] + ((sg + 1 > t_b) ? -1e9f : 0.f);
                aq[nt][0] = v0; aq[nt][1] = v1; aq[nt][2] = v2; aq[nt][3] = v3;
                *(float2*)&qkout[((size_t)bh * T_ + t_a) * T_ + sg] = make_float2(v0, v1);
                *(float2*)&qkout[((size_t)bh * T_ + t_b) * T_ + sg] = make_float2(v2, v3);
                rmx_a = fmaxf(rmx_a, fmaxf(v0, v1));
                rmx_b = fmaxf(rmx_b, fmaxf(v2, v3));
            }
            rmx_a = fmaxf(rmx_a, __shfl_xor_sync(0xFFFFFFFF, rmx_a, 1));
            rmx_a = fmaxf(rmx_a, __shfl_xor_sync(0xFFFFFFFF, rmx_a, 2));
            rmx_b = fmaxf(rmx_b, __shfl_xor_sync(0xFFFFFFFF, rmx_b, 1));
            rmx_b = fmaxf(rmx_b, __shfl_xor_sync(0xFFFFFFFF, rmx_b, 2));

            float nm_a = fmaxf(m_a, rmx_a), nm_b = fmaxf(m_b, rmx_b);
            float f_a = fexp(m_a - nm_a),   f_b = fexp(m_b - nm_b);
            m_a = nm_a; m_b = nm_b;

            float p[4][4];
            float ps_a = 0.f, ps_b = 0.f;
            #pragma unroll
            for (int nt = 0; nt < 4; nt++) {
                p[nt][0] = fexp(aq[nt][0] - m_a);
                p[nt][1] = fexp(aq[nt][1] - m_a);
                p[nt][2] = fexp(aq[nt][2] - m_b);
                p[nt][3] = fexp(aq[nt][3] - m_b);
                ps_a += p[nt][0] + p[nt][1];
                ps_b += p[nt][2] + p[nt][3];
            }
            ps_a += __shfl_xor_sync(0xFFFFFFFF, ps_a, 1);
            ps_a += __shfl_xor_sync(0xFFFFFFFF, ps_a, 2);
            ps_b += __shfl_xor_sync(0xFFFFFFFF, ps_b, 1);
            ps_b += __shfl_xor_sync(0xFFFFFFFF, ps_b, 2);
            rs_a = rs_a * f_a + ps_a;
            rs_b = rs_b * f_b + ps_b;
            #pragma unroll
            for (int nt = 0; nt < 8; nt++) {
                aw[nt][0] *= f_a; aw[nt][1] *= f_a;
                aw[nt][2] *= f_b; aw[nt][3] *= f_b;
            }

            #pragma unroll
            for (int kg = 0; kg < 2; kg++) {
                uint32_t pa_h[4], pa_l[4];
                split2(p[2 * kg][0],     p[2 * kg][1],     pa_h[0], pa_l[0]);
                split2(p[2 * kg][2],     p[2 * kg][3],     pa_h[1], pa_l[1]);
                split2(p[2 * kg + 1][0], p[2 * kg + 1][1], pa_h[2], pa_l[2]);
                split2(p[2 * kg + 1][2], p[2 * kg + 1][3], pa_h[3], pa_l[3]);
                #pragma unroll
                for (int o = 0; o < 4; o++) {
                    uint32_t vb = smb + (uint32_t)((30720 + cur * 5120) * 2)
                                + vboff + (uint32_t)(o * (16 * PITCH * 2)) + (uint32_t)(kg * 32);
                    uint32_t vh2[2][2], vl2[2][2];
                    ldsm_x4(vh2[0][0], vh2[0][1], vh2[1][0], vh2[1][1], vb);
                    ldsm_x4(vl2[0][0], vl2[0][1], vl2[1][0], vl2[1][1], vb + 5120);
                    mma_bf16(aw[o * 2],     pa_h, vh2[0]);
                    mma_bf16(aw[o * 2],     pa_h, vl2[0]);
                    mma_bf16(aw[o * 2],     pa_l, vh2[0]);
                    mma_bf16(aw[o * 2 + 1], pa_h, vh2[1]);
                    mma_bf16(aw[o * 2 + 1], pa_h, vl2[1]);
                    mma_bf16(aw[o * 2 + 1], pa_l, vh2[1]);
                }
            }
        } else {
            float2 mv = make_float2(-1e9f, -1e9f);
            #pragma unroll
            for (int nt = 0; nt < 4; nt++) {
                int sg = s0 + (nt << 3) + c2;
                *(float2*)&qkout[((size_t)bh * T_ + t_a) * T_ + sg] = mv;
                *(float2*)&qkout[((size_t)bh * T_ + t_b) * T_ + sg] = mv;
            }
        }
        cur ^= 1;
    }

    // epilogue: divide by row sum, split-write to g_ah/g_al
    {
        float ri_a = 1.0f / rs_a, ri_b = 1.0f / rs_b;
        int m0 = t0 + (w << 4) + rA;
        #pragma unroll
        for (int nt = 0; nt < 8; nt++) {
            int n0 = h * HD_ + (nt << 3) + c2;
            size_t o0 = (size_t)(b * T_ + m0) * D_ + n0;
            size_t o1 = (size_t)(b * T_ + m0 + 8) * D_ + n0;
            uint32_t hh, ll;
            split2(aw[nt][0] * ri_a, aw[nt][1] * ri_a, hh, ll);
            *(uint32_t*)&g_ah[o0] = hh; *(uint32_t*)&g_al[o0] = ll;
            split2(aw[nt][2] * ri_b, aw[nt][3] * ri_b, hh, ll);
            *(uint32_t*)&g_ah[o1] = hh; *(uint32_t*)&g_al[o1] = ll;
        }
    }
}

// ---------------------------------------------------------------------------
extern "C" void kernel_launch(void* const* d_in, const int* in_sizes, int n_in,
                              void* d_out, int out_size)
{
    const float* x    = (const float*)d_in[0];
    const float* cosp = (const float*)d_in[2];
    const float* sinp = (const float*)d_in[3];
    const float* Wq   = (const float*)d_in[4];
    const float* bq   = (const float*)d_in[5];
    const float* Wk   = (const float*)d_in[6];
    const float* Wv   = (const float*)d_in[7];
    const float* bv   = (const float*)d_in[8];
    const float* Wo   = (const float*)d_in[9];
    const float* bo   = (const float*)d_in[10];

    float* out = (float*)d_out;
    float* qk  = out + (size_t)M_ * D_;

    static bool attr_done = false;
    if (!attr_done) {
        cudaFuncSetAttribute(gemm_qkv, cudaFuncAttributeMaxDynamicSharedMemorySize, GSMEM);
        cudaFuncSetAttribute(gemm_out, cudaFuncAttributeMaxDynamicSharedMemorySize, GSMEM);
        cudaFuncSetAttribute(att_fused, cudaFuncAttributeMaxDynamicSharedMemorySize, ATT_SMEM);
        attr_done = true;
    }

    presplit_all<<<4096, 256>>>(x, Wq, Wk, Wv, Wo);

    gemm_qkv<<<dim3(3 * D_ / 64, M_ / 128), 256, GSMEM>>>(cosp, sinp, bq, bv, qk);

    att_fused<<<dim3(T_ / 128, B_ * H_), 256, ATT_SMEM>>>(qk);

    gemm_out<<<dim3(D_ / 64, M_ / 128), 256, GSMEM>>>(bo, out);
}

// round 17
// speedup vs baseline: 1.0802x; 1.0802x over previous
#include <cuda_runtime.h>
#include <cuda_bf16.h>
#include <cstdint>

#define B_  2
#define T_  2048
#define D_  1024
#define H_  16
#define HD_ 64
#define M_  (B_*T_)   // 4096
#define PITCH 40      // bf16 per smem row: 80B, conflict-free for LDSM

// bf16 hi/lo split operands
__device__ __nv_bfloat16 g_xh[M_*D_],  g_xl[M_*D_];
__device__ __nv_bfloat16 g_qh[M_*D_],  g_ql[M_*D_];
__device__ __nv_bfloat16 g_kh[M_*D_],  g_kl[M_*D_];
__device__ __nv_bfloat16 g_vh[M_*D_],  g_vl[M_*D_];
__device__ __nv_bfloat16 g_ah[M_*D_],  g_al[M_*D_];     // attention out
__device__ __nv_bfloat16 w_qkvh[3*D_*D_], w_qkvl[3*D_*D_];
__device__ __nv_bfloat16 w_oh[D_*D_],  w_ol[D_*D_];

// Fast exp on the FMA pipe.
__device__ __forceinline__ float fexp(float x) {
    float y = fmaxf(x * 1.44269504f, -126.0f);
    float z = y + 12582912.0f;
    int   n = __float_as_int(z) - 0x4B400000;
    float f = y - (z - 12582912.0f);
    float p = 1.3333558e-3f;
    p = fmaf(p, f, 9.6181291e-3f);
    p = fmaf(p, f, 5.5504109e-2f);
    p = fmaf(p, f, 2.4022651e-1f);
    p = fmaf(p, f, 6.9314718e-1f);
    p = fmaf(p, f, 1.0f);
    return p * __int_as_float((n << 23) + 0x3F800000);
}

__device__ __forceinline__ void mma_bf16(float* c, const uint32_t* a, const uint32_t* b) {
    asm volatile(
        "mma.sync.aligned.m16n8k16.row.col.f32.bf16.bf16.f32 "
        "{%0,%1,%2,%3}, {%4,%5,%6,%7}, {%8,%9}, {%0,%1,%2,%3};\n"
        : "+f"(c[0]), "+f"(c[1]), "+f"(c[2]), "+f"(c[3])
        : "r"(a[0]), "r"(a[1]), "r"(a[2]), "r"(a[3]), "r"(b[0]), "r"(b[1]));
}

__device__ __forceinline__ void ldsm_x4(uint32_t& r0, uint32_t& r1, uint32_t& r2,
                                        uint32_t& r3, uint32_t addr) {
    asm volatile("ldmatrix.sync.aligned.m8n8.x4.shared.b16 {%0,%1,%2,%3}, [%4];"
                 : "=r"(r0), "=r"(r1), "=r"(r2), "=r"(r3) : "r"(addr));
}

__device__ __forceinline__ uint32_t smem_u32(const void* p) {
    return (uint32_t)__cvta_generic_to_shared(p);
}

__device__ __forceinline__ void split2(float a, float b, uint32_t& hi, uint32_t& lo) {
    __nv_bfloat16 ah = __float2bfloat16(a);
    __nv_bfloat16 bh = __float2bfloat16(b);
    __nv_bfloat16 al = __float2bfloat16(a - __bfloat162float(ah));
    __nv_bfloat16 bl = __float2bfloat16(b - __bfloat162float(bh));
    hi = (uint32_t)__bfloat16_as_ushort(ah) | ((uint32_t)__bfloat16_as_ushort(bh) << 16);
    lo = (uint32_t)__bfloat16_as_ushort(al) | ((uint32_t)__bfloat16_as_ushort(bl) << 16);
}

__device__ __forceinline__ void cpa16(void* s, const void* g) {
    uint32_t sa = (uint32_t)__cvta_generic_to_shared(s);
    asm volatile("cp.async.ca.shared.global [%0], [%1], 16;\n" :: "r"(sa), "l"(g));
}

__device__ __forceinline__ void stg_cs4(float* p, float4 v) {
    asm volatile("st.global.cs.v4.f32 [%0], {%1,%2,%3,%4};"
                 :: "l"(p), "f"(v.x), "f"(v.y), "f"(v.z), "f"(v.w) : "memory");
}

// ---------------------------------------------------------------------------
// presplit_all: fp32 -> bf16 hi/lo for x + all four weights, one launch.
// ---------------------------------------------------------------------------
__global__ void __launch_bounds__(256) presplit_all(
    const float* __restrict__ x,  const float* __restrict__ Wq,
    const float* __restrict__ Wk, const float* __restrict__ Wv,
    const float* __restrict__ Wo)
{
    #pragma unroll
    for (int u = 0; u < 2; u++) {
        int idx = (blockIdx.x * 512) + (u << 8) + threadIdx.x;   // < 2097152
        const float* s;
        __nv_bfloat16 *dh, *dl;
        int off;
        if (idx < 1048576) {
            s = x; dh = g_xh; dl = g_xl; off = idx;
        } else {
            int r = idx - 1048576;
            int w = r >> 18;
            off = r & 262143;
            if (w == 0)      { s = Wq; dh = w_qkvh;             dl = w_qkvl; }
            else if (w == 1) { s = Wk; dh = w_qkvh + D_*D_;     dl = w_qkvl + D_*D_; }
            else if (w == 2) { s = Wv; dh = w_qkvh + 2*D_*D_;   dl = w_qkvl + 2*D_*D_; }
            else             { s = Wo; dh = w_oh;               dl = w_ol; }
        }
        float4 v = ((const float4*)s)[off];
        uint32_t h0, l0, h1, l1;
        split2(v.x, v.y, h0, l0);
        split2(v.z, v.w, h1, l1);
        ((uint2*)dh)[off] = make_uint2(h0, h1);
        ((uint2*)dl)[off] = make_uint2(l0, l1);
    }
}

// ===========================================================================
// Dense GEMM: CTA tile 128x128, warp tile 64x32 (8 warps = 2M x 4N),
// k-step 32, 2-stage cp.async pipeline.
// Stage layout (bytes): Ah@0 Al@10240 Bh@20480 Bl@30720, stage=40960.
// ===========================================================================
#define STGE  (512*PITCH)    // bf16 elems per stage (20480)
#define STGB2 (STGE*2)       // 40960 bytes
#define OAlB  (128*PITCH*2)  // 10240
#define OBhB  (256*PITCH*2)  // 20480
#define OBlB  (384*PITCH*2)  // 30720
#define GSMEM (2*STGB2)      // 81920

#define GEMM_PREFETCH(Ahp, Alp, Whp, Wlp)                                         \
    auto prefetch = [&](int kt, int slot) {                                       \
        int k0 = kt << 5;                                                         \
        __nv_bfloat16* st = sm + slot * STGE;                                     \
        _Pragma("unroll")                                                         \
        for (int i = 0; i < 2; i++) {                                             \
            int c = tid + (i << 8);                                               \
            int r = c >> 2, cq = (c & 3) << 3;                                    \
            cpa16(&st[r * PITCH + cq],               &Ahp[(size_t)(bm + r) * D_ + k0 + cq]); \
            cpa16(&st[128 * PITCH + r * PITCH + cq], &Alp[(size_t)(bm + r) * D_ + k0 + cq]); \
            cpa16(&st[256 * PITCH + r * PITCH + cq], &Whp[(size_t)(bn + r) * D_ + k0 + cq]); \
            cpa16(&st[384 * PITCH + r * PITCH + cq], &Wlp[(size_t)(bn + r) * D_ + k0 + cq]); \
        }                                                                         \
        asm volatile("cp.async.commit_group;\n");                                 \
    };

#define GEMM_MAINLOOP()                                                           \
    float acc[4][4][4] = {};                                                      \
    prefetch(0, 0);                                                               \
    prefetch(1, 1);                                                               \
    const int KT = D_ / 32;                                                       \
    for (int kt = 0; kt < KT; kt++) {                                             \
        asm volatile("cp.async.wait_group 1;\n");                                 \
        __syncthreads();                                                          \
        const uint32_t stb = smb + (uint32_t)(kt & 1) * STGB2;                    \
        _Pragma("unroll")                                                         \
        for (int ks = 0; ks < 32; ks += 16) {                                     \
            const uint32_t ka = ks * 2;                                           \
            uint32_t ah[4][4], bh[4][2];                                          \
            _Pragma("unroll")                                                     \
            for (int mt = 0; mt < 4; mt++)                                        \
                ldsm_x4(ah[mt][0], ah[mt][1], ah[mt][2], ah[mt][3],               \
                        stb + aoff0 + ka + (uint32_t)(mt * (16 * PITCH * 2)));    \
            ldsm_x4(bh[0][0], bh[0][1], bh[1][0], bh[1][1], stb + OBhB + boff0 + ka); \
            ldsm_x4(bh[2][0], bh[2][1], bh[3][0], bh[3][1],                       \
                    stb + OBhB + boff0 + ka + 16 * PITCH * 2);                    \
            _Pragma("unroll")                                                     \
            for (int mt = 0; mt < 4; mt++)                                        \
                _Pragma("unroll")                                                 \
                for (int nt = 0; nt < 4; nt++)                                    \
                    mma_bf16(acc[mt][nt], ah[mt], bh[nt]);                        \
            uint32_t bl[4][2];                                                    \
            ldsm_x4(bl[0][0], bl[0][1], bl[1][0], bl[1][1], stb + OBlB + boff0 + ka); \
            ldsm_x4(bl[2][0], bl[2][1], bl[3][0], bl[3][1],                       \
                    stb + OBlB + boff0 + ka + 16 * PITCH * 2);                    \
            _Pragma("unroll")                                                     \
            for (int mt = 0; mt < 4; mt++)                                        \
                _Pragma("unroll")                                                 \
                for (int nt = 0; nt < 4; nt++)                                    \
                    mma_bf16(acc[mt][nt], ah[mt], bl[nt]);                        \
            uint32_t al4[4][4];                                                   \
            _Pragma("unroll")                                                     \
            for (int mt = 0; mt < 4; mt++)                                        \
                ldsm_x4(al4[mt][0], al4[mt][1], al4[mt][2], al4[mt][3],           \
                        stb + OAlB + aoff0 + ka + (uint32_t)(mt * (16 * PITCH * 2))); \
            _Pragma("unroll")                                                     \
            for (int mt = 0; mt < 4; mt++)                                        \
                _Pragma("unroll")                                                 \
                for (int nt = 0; nt < 4; nt++)                                    \
                    mma_bf16(acc[mt][nt], al4[mt], bh[nt]);                       \
        }                                                                         \
        __syncthreads();                                                          \
        if (kt + 2 < KT) prefetch(kt + 2, kt & 1);                                \
        else asm volatile("cp.async.commit_group;\n");                            \
    }

// ---------------------------------------------------------------------------
// QKV GEMM with fused bias/RoPE/scale/split epilogue + masked-qk fill.
// ---------------------------------------------------------------------------
__global__ void __launch_bounds__(256, 2) gemm_qkv(
    const float* __restrict__ cosp, const float* __restrict__ sinp,
    const float* __restrict__ bq, const float* __restrict__ bv,
    float* __restrict__ qkC)
{
    extern __shared__ __align__(16) __nv_bfloat16 sm[];

    const int tid = threadIdx.x, lane = tid & 31, wid = tid >> 5;
    const int wm = (wid & 1) << 6, wn = (wid >> 1) << 5;
    const int bm = blockIdx.y << 7, bn = blockIdx.x << 7;
    const int m8 = lane >> 3, r8 = lane & 7;
    const uint32_t smb = smem_u32(sm);

    const uint32_t aoff0 = ((uint32_t)((wm + r8 + ((m8 & 1) << 3)) * PITCH
                                       + ((m8 >> 1) << 3))) * 2;
    const uint32_t boff0 = ((uint32_t)((wn + r8 + ((m8 >> 1) << 3)) * PITCH
                                       + ((m8 & 1) << 3))) * 2;

    // masked qk fill (fire-and-forget streaming stores)
    {
        const int flat = blockIdx.x + gridDim.x * blockIdx.y;   // 0..767
        const float4 mv = make_float4(-1e9f, -1e9f, -1e9f, -1e9f);
        for (int t = flat; t < 3840; t += 768) {
            int bh2 = t / 120;
            int p = t - bh2 * 120;
            int i = 0, a2 = 0;
            while (a2 + (15 - i) <= p) { a2 += (15 - i); i++; }
            int j = p - a2;
            int r0 = i << 7;
            int c0 = ((i + 1 + j) << 7);
            #pragma unroll 4
            for (int e = tid; e < 4096; e += 256) {
                int r = e >> 5, cc = (e & 31) << 2;
                stg_cs4(&qkC[((size_t)bh2 * T_ + r0 + r) * T_ + c0 + cc], mv);
            }
        }
    }

    GEMM_PREFETCH(g_xh, g_xl, w_qkvh, w_qkvl)
    GEMM_MAINLOOP()

    const int seg = bn >> 10;
    __nv_bfloat16* dh = (seg == 0) ? g_qh : (seg == 1) ? g_kh : g_vh;
    __nv_bfloat16* dl = (seg == 0) ? g_ql : (seg == 1) ? g_kl : g_vl;
    const float scale = 0.35355339059327373f;

    #pragma unroll
    for (int mt = 0; mt < 4; mt++) {
        int m0 = bm + wm + (mt << 4) + (lane >> 2);
        int ta = m0 & (T_ - 1), tb = ta + 8;
        #pragma unroll
        for (int nt = 0; nt < 4; nt++) {
            int ng = bn + wn + (nt << 3) + ((lane & 3) << 1);
            int nloc = ng & 1023;
            float v00 = acc[mt][nt][0], v01 = acc[mt][nt][1];
            float v10 = acc[mt][nt][2], v11 = acc[mt][nt][3];
            if (seg == 0) { v00 += bq[nloc]; v01 += bq[nloc + 1];
                            v10 += bq[nloc]; v11 += bq[nloc + 1]; }
            else if (seg == 2) { v00 += bv[nloc]; v01 += bv[nloc + 1];
                                 v10 += bv[nloc]; v11 += bv[nloc + 1]; }
            if (seg < 2) {
                int p = (nloc & 63) >> 1;
                float ca = cosp[ta * 32 + p], sa = sinp[ta * 32 + p];
                float cb = cosp[tb * 32 + p], sb = sinp[tb * 32 + p];
                float o00 = (v00 * ca - v01 * sa) * scale;
                float o01 = (v00 * sa + v01 * ca) * scale;
                float o10 = (v10 * cb - v11 * sb) * scale;
                float o11 = (v10 * sb + v11 * cb) * scale;
                v00 = o00; v01 = o01; v10 = o10; v11 = o11;
            }
            uint32_t h, l;
            split2(v00, v01, h, l);
            *(uint32_t*)&dh[(size_t)m0 * D_ + nloc] = h;
            *(uint32_t*)&dl[(size_t)m0 * D_ + nloc] = l;
            split2(v10, v11, h, l);
            *(uint32_t*)&dh[(size_t)(m0 + 8) * D_ + nloc] = h;
            *(uint32_t*)&dl[(size_t)(m0 + 8) * D_ + nloc] = l;
        }
    }
}

// ---------------------------------------------------------------------------
// Output GEMM: out = wv @ Wo^T + bo (fp32 out)
// ---------------------------------------------------------------------------
__global__ void __launch_bounds__(256, 2) gemm_out(
    const float* __restrict__ bias, float* __restrict__ Cf)
{
    extern __shared__ __align__(16) __nv_bfloat16 sm[];

    const int tid = threadIdx.x, lane = tid & 31, wid = tid >> 5;
    const int wm = (wid & 1) << 6, wn = (wid >> 1) << 5;
    const int bm = blockIdx.y << 7, bn = blockIdx.x << 7;
    const int m8 = lane >> 3, r8 = lane & 7;
    const uint32_t smb = smem_u32(sm);

    const uint32_t aoff0 = ((uint32_t)((wm + r8 + ((m8 & 1) << 3)) * PITCH
                                       + ((m8 >> 1) << 3))) * 2;
    const uint32_t boff0 = ((uint32_t)((wn + r8 + ((m8 >> 1) << 3)) * PITCH
                                       + ((m8 & 1) << 3))) * 2;

    GEMM_PREFETCH(g_ah, g_al, w_oh, w_ol)
    GEMM_MAINLOOP()

    #pragma unroll
    for (int mt = 0; mt < 4; mt++) {
        int m0 = bm + wm + (mt << 4) + (lane >> 2);
        #pragma unroll
        for (int nt = 0; nt < 4; nt++) {
            int n0 = bn + wn + (nt << 3) + ((lane & 3) << 1);
            float b0 = bias[n0], b1 = bias[n0 + 1];
            *(float2*)&Cf[(size_t)m0 * D_ + n0] =
                make_float2(acc[mt][nt][0] + b0, acc[mt][nt][1] + b1);
            *(float2*)&Cf[(size_t)(m0 + 8) * D_ + n0] =
                make_float2(acc[mt][nt][2] + b0, acc[mt][nt][3] + b1);
        }
    }
}

// ---------------------------------------------------------------------------
// Fused attention, FA2-style; longest t-blocks scheduled first. (unchanged)
// ---------------------------------------------------------------------------
#define ATT_SMEM (40960 * 2)

__global__ void __launch_bounds__(256, 2) att_fused(float* __restrict__ qkout)
{
    extern __shared__ __align__(16) __nv_bfloat16 dsm[];

    const int tid  = threadIdx.x;
    const int lane = tid & 31;
    const int w    = tid >> 5;
    const int bh   = blockIdx.y;
    const int b    = bh >> 4, h = bh & 15;
    const int t0   = ((int)(gridDim.x - 1 - blockIdx.x)) << 7;
    const int m8 = lane >> 3, r8 = lane & 7;
    const int rA = lane >> 2;
    const int c2 = (lane & 3) << 1;

    const uint32_t smb = smem_u32(dsm);

    const uint32_t aoffQ = ((uint32_t)(((w << 4) + r8 + ((m8 & 1) << 3)) * PITCH
                                       + ((m8 >> 1) << 3))) * 2;
    const uint32_t kboff = ((uint32_t)((r8 + ((m8 >> 1) << 3)) * PITCH
                                       + ((m8 & 1) << 3))) * 2;
    const uint32_t vboff = kboff;

    const __nv_bfloat16* Qh = g_qh + (size_t)b * T_ * D_ + h * HD_;
    const __nv_bfloat16* Ql = g_ql + (size_t)b * T_ * D_ + h * HD_;
    const __nv_bfloat16* Kh = g_kh + (size_t)b * T_ * D_ + h * HD_;
    const __nv_bfloat16* Kl = g_kl + (size_t)b * T_ * D_ + h * HD_;
    const __nv_bfloat16* Vh = g_vh + (size_t)b * T_ * D_ + h * HD_;
    const __nv_bfloat16* Vl = g_vl + (size_t)b * T_ * D_ + h * HD_;

    #pragma unroll
    for (int i = 0; i < 4; i++) {
        int idx = tid + (i << 8);
        int r = idx >> 3, c8 = idx & 7;
        int col = c8 << 3, ch = col >> 5, cc = col & 31;
        int de = ch * 5120 + r * PITCH + cc;
        *(uint4*)&dsm[de]         = *(const uint4*)&Qh[(size_t)(t0 + r) * D_ + col];
        *(uint4*)&dsm[10240 + de] = *(const uint4*)&Ql[(size_t)(t0 + r) * D_ + col];
    }

    auto kfill = [&](int s0, int buf) {
        int r = tid >> 3, c8 = tid & 7;
        int col = c8 << 3, ch = col >> 5, cc = col & 31;
        uint32_t de = 20480 + buf * 5120 + ch * 1280 + r * PITCH + cc;
        cpa16(&dsm[de],        &Kh[(size_t)(s0 + r) * D_ + col]);
        cpa16(&dsm[de + 2560], &Kl[(size_t)(s0 + r) * D_ + col]);
        asm volatile("cp.async.commit_group;\n");
    };

    uint2 vrh[2], vrl[2];
    auto vload = [&](int s0) {
        #pragma unroll
        for (int i = 0; i < 2; i++) {
            int fi = tid + (i << 8);
            int s = fi >> 4, hq = (fi & 15) << 2;
            vrh[i] = *(const uint2*)&Vh[(size_t)(s0 + s) * D_ + hq];
            vrl[i] = *(const uint2*)&Vl[(size_t)(s0 + s) * D_ + hq];
        }
    };
    auto vstore = [&](int buf) {
        #pragma unroll
        for (int i = 0; i < 2; i++) {
            int fi = tid + (i << 8);
            int s = fi >> 4, hq = (fi & 15) << 2;
            const __nv_bfloat16* ph = (const __nv_bfloat16*)&vrh[i];
            const __nv_bfloat16* pl = (const __nv_bfloat16*)&vrl[i];
            #pragma unroll
            for (int j = 0; j < 4; j++) {
                dsm[30720 + buf * 5120 + (hq + j) * PITCH + s]        = ph[j];
                dsm[30720 + buf * 5120 + 2560 + (hq + j) * PITCH + s] = pl[j];
            }
        }
    };

    float aw[8][4] = {};
    float m_a = -1e30f, m_b = -1e30f, rs_a = 0.f, rs_b = 0.f;

    kfill(0, 0);
    vload(0);

    const int ntiles = (t0 >> 5) + 4;
    int cur = 0;
    const int t_a = t0 + (w << 4) + rA;
    const int t_b = t_a + 8;

    for (int it = 0; it < ntiles; it++) {
        const int s0 = it << 5;
        vstore(cur);
        asm volatile("cp.async.wait_group 0;\n");
        __syncthreads();
        if (it + 1 < ntiles) {
            kfill((it + 1) << 5, cur ^ 1);
            vload((it + 1) << 5);
        }

        const bool active = (s0 < t0 + (w << 4) + 16);
        if (active) {
            float aq[4][4] = {};
            #pragma unroll
            for (int c = 0; c < 2; c++) {
                #pragma unroll
                for (int ks = 0; ks < 32; ks += 16) {
                    const uint32_t ka = ks * 2;
                    uint32_t qh4[4], ql4[4], kh2[4][2], kl2[4][2];
                    uint32_t qb = smb + (uint32_t)(c * 10240) + aoffQ + ka;
                    ldsm_x4(qh4[0], qh4[1], qh4[2], qh4[3], qb);
                    ldsm_x4(ql4[0], ql4[1], ql4[2], ql4[3], qb + 20480);
                    uint32_t kb = smb + (uint32_t)((20480 + cur * 5120 + c * 1280) * 2)
                                + kboff + ka;
                    ldsm_x4(kh2[0][0], kh2[0][1], kh2[1][0], kh2[1][1], kb);
                    ldsm_x4(kh2[2][0], kh2[2][1], kh2[3][0], kh2[3][1], kb + 16 * PITCH * 2);
                    ldsm_x4(kl2[0][0], kl2[0][1], kl2[1][0], kl2[1][1], kb + 5120);
                    ldsm_x4(kl2[2][0], kl2[2][1], kl2[3][0], kl2[3][1], kb + 5120 + 16 * PITCH * 2);
                    #pragma unroll
                    for (int nt = 0; nt < 4; nt++) {
                        mma_bf16(aq[nt], qh4, kh2[nt]);
                        mma_bf16(aq[nt], qh4, kl2[nt]);
                        mma_bf16(aq[nt], ql4, kh2[nt]);
                    }
                }
            }

            float rmx_a = -1e30f, rmx_b = -1e30f;
            #pragma unroll
            for (int nt = 0; nt < 4; nt++) {
                int sg = s0 + (nt << 3) + c2;
                float v0 = aq[nt][0] + ((sg     > t_a) ? -1e9f : 0.f);
                float v1 = aq[nt][1] + ((sg + 1 > t_a) ? -1e9f : 0.f);
                float v2 = aq[nt][2] + ((sg     > t_b) ? -1e9f : 0.f);
                float v3 = aq[nt][3] + ((sg + 1 > t_b) ? -1e9f : 0.f);
                aq[nt][0] = v0; aq[nt][1] = v1; aq[nt][2] = v2; aq[nt][3] = v3;
                *(float2*)&qkout[((size_t)bh * T_ + t_a) * T_ + sg] = make_float2(v0, v1);
                *(float2*)&qkout[((size_t)bh * T_ + t_b) * T_ + sg] = make_float2(v2, v3);
                rmx_a = fmaxf(rmx_a, fmaxf(v0, v1));
                rmx_b = fmaxf(rmx_b, fmaxf(v2, v3));
            }
            rmx_a = fmaxf(rmx_a, __shfl_xor_sync(0xFFFFFFFF, rmx_a, 1));
            rmx_a = fmaxf(rmx_a, __shfl_xor_sync(0xFFFFFFFF, rmx_a, 2));
            rmx_b = fmaxf(rmx_b, __shfl_xor_sync(0xFFFFFFFF, rmx_b, 1));
            rmx_b = fmaxf(rmx_b, __shfl_xor_sync(0xFFFFFFFF, rmx_b, 2));

            float nm_a = fmaxf(m_a, rmx_a), nm_b = fmaxf(m_b, rmx_b);
            float f_a = fexp(m_a - nm_a),   f_b = fexp(m_b - nm_b);
            m_a = nm_a; m_b = nm_b;

            float p[4][4];
            float ps_a = 0.f, ps_b = 0.f;
            #pragma unroll
            for (int nt = 0; nt < 4; nt++) {
                p[nt][0] = fexp(aq[nt][0] - m_a);
                p[nt][1] = fexp(aq[nt][1] - m_a);
                p[nt][2] = fexp(aq[nt][2] - m_b);
                p[nt][3] = fexp(aq[nt][3] - m_b);
                ps_a += p[nt][0] + p[nt][1];
                ps_b += p[nt][2] + p[nt][3];
            }
            ps_a += __shfl_xor_sync(0xFFFFFFFF, ps_a, 1);
            ps_a += __shfl_xor_sync(0xFFFFFFFF, ps_a, 2);
            ps_b += __shfl_xor_sync(0xFFFFFFFF, ps_b, 1);
            ps_b += __shfl_xor_sync(0xFFFFFFFF, ps_b, 2);
            rs_a = rs_a * f_a + ps_a;
            rs_b = rs_b * f_b + ps_b;
            #pragma unroll
            for (int nt = 0; nt < 8; nt++) {
                aw[nt][0] *= f_a; aw[nt][1] *= f_a;
                aw[nt][2] *= f_b; aw[nt][3] *= f_b;
            }

            #pragma unroll
            for (int kg = 0; kg < 2; kg++) {
                uint32_t pa_h[4], pa_l[4];
                split2(p[2 * kg][0],     p[2 * kg][1],     pa_h[0], pa_l[0]);
                split2(p[2 * kg][2],     p[2 * kg][3],     pa_h[1], pa_l[1]);
                split2(p[2 * kg + 1][0], p[2 * kg + 1][1], pa_h[2], pa_l[2]);
                split2(p[2 * kg + 1][2], p[2 * kg + 1][3], pa_h[3], pa_l[3]);
                #pragma unroll
                for (int o = 0; o < 4; o++) {
                    uint32_t vb = smb + (uint32_t)((30720 + cur * 5120) * 2)
                                + vboff + (uint32_t)(o * (16 * PITCH * 2)) + (uint32_t)(kg * 32);
                    uint32_t vh2[2][2], vl2[2][2];
                    ldsm_x4(vh2[0][0], vh2[0][1], vh2[1][0], vh2[1][1], vb);
                    ldsm_x4(vl2[0][0], vl2[0][1], vl2[1][0], vl2[1][1], vb + 5120);
                    mma_bf16(aw[o * 2],     pa_h, vh2[0]);
                    mma_bf16(aw[o * 2],     pa_h, vl2[0]);
                    mma_bf16(aw[o * 2],     pa_l, vh2[0]);
                    mma_bf16(aw[o * 2 + 1], pa_h, vh2[1]);
                    mma_bf16(aw[o * 2 + 1], pa_h, vl2[1]);
                    mma_bf16(aw[o * 2 + 1], pa_l, vh2[1]);
                }
            }
        } else {
            float2 mv = make_float2(-1e9f, -1e9f);
            #pragma unroll
            for (int nt = 0; nt < 4; nt++) {
                int sg = s0 + (nt << 3) + c2;
                *(float2*)&qkout[((size_t)bh * T_ + t_a) * T_ + sg] = mv;
                *(float2*)&qkout[((size_t)bh * T_ + t_b) * T_ + sg] = mv;
            }
        }
        cur ^= 1;
    }

    {
        float ri_a = 1.0f / rs_a, ri_b = 1.0f / rs_b;
        int m0 = t0 + (w << 4) + rA;
        #pragma unroll
        for (int nt = 0; nt < 8; nt++) {
            int n0 = h * HD_ + (nt << 3) + c2;
            size_t o0 = (size_t)(b * T_ + m0) * D_ + n0;
            size_t o1 = (size_t)(b * T_ + m0 + 8) * D_ + n0;
            uint32_t hh, ll;
            split2(aw[nt][0] * ri_a, aw[nt][1] * ri_a, hh, ll);
            *(uint32_t*)&g_ah[o0] = hh; *(uint32_t*)&g_al[o0] = ll;
            split2(aw[nt][2] * ri_b, aw[nt][3] * ri_b, hh, ll);
            *(uint32_t*)&g_ah[o1] = hh; *(uint32_t*)&g_al[o1] = ll;
        }
    }
}

// ---------------------------------------------------------------------------
extern "C" void kernel_launch(void* const* d_in, const int* in_sizes, int n_in,
                              void* d_out, int out_size)
{
    const float* x    = (const float*)d_in[0];
    const float* cosp = (const float*)d_in[2];
    const float* sinp = (const float*)d_in[3];
    const float* Wq   = (const float*)d_in[4];
    const float* bq   = (const float*)d_in[5];
    const float* Wk   = (const float*)d_in[6];
    const float* Wv   = (const float*)d_in[7];
    const float* bv   = (const float*)d_in[8];
    const float* Wo   = (const float*)d_in[9];
    const float* bo   = (const float*)d_in[10];

    float* out = (float*)d_out;
    float* qk  = out + (size_t)M_ * D_;

    static bool attr_done = false;
    if (!attr_done) {
        cudaFuncSetAttribute(gemm_qkv, cudaFuncAttributeMaxDynamicSharedMemorySize, GSMEM);
        cudaFuncSetAttribute(gemm_out, cudaFuncAttributeMaxDynamicSharedMemorySize, GSMEM);
        cudaFuncSetAttribute(att_fused, cudaFuncAttributeMaxDynamicSharedMemorySize, ATT_SMEM);
        attr_done = true;
    }

    presplit_all<<<4096, 256>>>(x, Wq, Wk, Wv, Wo);

    gemm_qkv<<<dim3(3 * D_ / 128, M_ / 128), 256, GSMEM>>>(cosp, sinp, bq, bv, qk);

    att_fused<<<dim3(T_ / 128, B_ * H_), 256, ATT_SMEM>>>(qk);

    gemm_out<<<dim3(D_ / 128, M_ / 128), 256, GSMEM>>>(bo, out);
}